// round 4
// baseline (speedup 1.0000x reference)
#include <cuda_runtime.h>
#include <cstdint>

// Problem constants
//  H=8, KB=8 cells; OB=64, IB=64, K=9, L=9; ZD=64, PD=16, DH=128
//  out: [512, 512, 9, 9] fp32 = 21,233,664 elements

__device__ float g_hid[64 * 128];       // relu(x @ W1^T + b1)
__device__ float g_exe[512 * 512 * 9];  // exe in [o][i][k] layout (matches unet [o][i][l])

// Packed f32x2 FMA (sm_103a): d = a*b + c elementwise on two fp32 lanes.
#define FMA_F32X2(d, a, b, c) \
    asm("fma.rn.f32x2 %0, %1, %2, %3;" : "=l"(d) : "l"(a), "l"(b), "l"(c))

// ---------------------------------------------------------------------------
// Kernel 1: hid[r][j] = relu(b1[j] + sum_t x[r][t] * W1[j][t]),  x = [z_all[r], pde]
// ---------------------------------------------------------------------------
__global__ __launch_bounds__(128)
void hypernet_hid(const float* __restrict__ z_all,
                  const float* __restrict__ W1,
                  const float* __restrict__ b1,
                  const float* __restrict__ pde)
{
    __shared__ float xs[80];
    const int r = blockIdx.x;
    const int j = threadIdx.x;
    if (j < 64)       xs[j] = z_all[r * 64 + j];
    else if (j < 80)  xs[j] = pde[j - 64];
    __syncthreads();

    const float4* wp = (const float4*)(W1 + j * 80);
    float acc = b1[j];
#pragma unroll
    for (int t = 0; t < 20; ++t) {
        float4 w = wp[t];
        acc = fmaf(w.x, xs[4*t+0], acc);
        acc = fmaf(w.y, xs[4*t+1], acc);
        acc = fmaf(w.z, xs[4*t+2], acc);
        acc = fmaf(w.w, xs[4*t+3], acc);
    }
    g_hid[r * 128 + j] = fmaxf(acc, 0.0f);
}

// ---------------------------------------------------------------------------
// Kernel 2: GEMM  exe[o,i,k] = hid[cell(o,i)] . W2[(obi)*9+k] + b2
//
// grid 1024: blockIdx.x = ob*16 + ibq  (ob in [0,64), ibq in [0,16) -> 4 ib)
// block 256: tid = cell*4 + ibl       (cell in [0,64), ibl in [0,4))
// Per block: 36 contiguous W2 rows, all 64 cells. One cell x 4-ib x 9-k... each
// thread computes 9 outputs (one cell, one ib, k=0..8) with f32x2 accumulators.
// smem 27.2 KB -> ~6-7 blocks/SM -> ~50 warps/SM.
// ---------------------------------------------------------------------------
__global__ __launch_bounds__(256, 6)
void gen_exe(const float* __restrict__ W2,
             const float* __restrict__ b2,
             float* __restrict__ exe_out)
{
    __shared__ float sm[6800];
    float* hs  = sm;            // [64][68]
    float* w2s = sm + 4352;     // [36][68]

    const int tid  = threadIdx.x;
    const int ob   = blockIdx.x >> 4;
    const int ibq  = blockIdx.x & 15;
    const int base9 = (ob * 64 + ibq * 4) * 9;   // first of 36 contiguous W2 rows

    const int cell = tid >> 2;
    const int ibl  = tid & 3;

    unsigned long long acc[9];
#pragma unroll
    for (int k = 0; k < 9; ++k) acc[k] = 0ull;

#pragma unroll 1
    for (int phase = 0; phase < 2; ++phase) {
        const int dbase = phase * 64;

        // hid half: 64 cells x 16 float4
        for (int idx = tid; idx < 1024; idx += 256) {
            int c = idx >> 4, q = idx & 15;
            float4 v = *(const float4*)(g_hid + c * 128 + dbase + 4 * q);
            *(float4*)(hs + c * 68 + 4 * q) = v;
        }
        // W2 half: 36 rows x 16 float4 (rows contiguous in global)
        for (int idx = tid; idx < 576; idx += 256) {
            int row = idx >> 4, q = idx & 15;
            float4 v = *(const float4*)(W2 + (size_t)(base9 + row) * 128 + dbase + 4 * q);
            *(float4*)(w2s + row * 68 + 4 * q) = v;
        }
        __syncthreads();

        const float* hp = hs + cell * 68;
        const float* wp = w2s + ibl * 9 * 68;
#pragma unroll
        for (int dd = 0; dd < 64; dd += 4) {
            ulonglong2 h = *(const ulonglong2*)(hp + dd);
#pragma unroll
            for (int k = 0; k < 9; ++k) {
                ulonglong2 w = *(const ulonglong2*)(wp + k * 68 + dd);
                FMA_F32X2(acc[k], h.x, w.x, acc[k]);
                FMA_F32X2(acc[k], h.y, w.y, acc[k]);
            }
        }
        __syncthreads();   // done reading this half before smem reuse
    }

    // ---- finalize into smem (alias over hs/w2s), then coalesced global write ----
    float* exe_s = sm;   // [64 cells][36]
#pragma unroll
    for (int k = 0; k < 9; ++k) {
        float2 p = *(float2*)&acc[k];
        exe_s[cell * 36 + ibl * 9 + k] = p.x + p.y + b2[base9 + ibl * 9 + k];
    }
    __syncthreads();

    // 2304 floats: 64 pieces of 36 contiguous floats in global
    for (int idx = tid; idx < 2304; idx += 256) {
        int c   = idx / 36;
        int off = idx - c * 36;
        int h = c >> 3, kb = c & 7;
        size_t gaddr = ((size_t)((h * 64 + ob) * 512 + kb * 64 + ibq * 4)) * 9 + off;
        exe_out[gaddr] = exe_s[idx];
    }
}

// ---------------------------------------------------------------------------
// Kernel 3: epilogue  out[p*81 + k*9 + l] = exe[p*9+k] * unet[p*9+l]
// p = o*512 + i runs over all 262144 pairs.
// grid 4096: block handles 64 consecutive pairs -> 5184 CONTIGUOUS out floats.
// block 256 threads, exe/unet staged in smem (576 floats each).
// ---------------------------------------------------------------------------
__global__ __launch_bounds__(256)
void epilogue(const float* __restrict__ exe,
              const float* __restrict__ unet,
              float* __restrict__ out)
{
    __shared__ float se[576];
    __shared__ float su[576];

    const int tid = threadIdx.x;
    const int bx  = blockIdx.x;

    const float4* e4 = (const float4*)(exe  + (size_t)bx * 576);
    const float4* u4 = (const float4*)(unet + (size_t)bx * 576);
    for (int idx = tid; idx < 144; idx += 256) {   // one iter (144<256)
        *(float4*)(se + 4 * idx) = e4[idx];
        *(float4*)(su + 4 * idx) = u4[idx];
    }
    __syncthreads();

    float4* o4 = (float4*)(out + (size_t)bx * 5184);
#pragma unroll 1
    for (int idx = tid; idx < 1296; idx += 256) {
        int e0 = idx << 2;
        int p  = e0 / 81;
        int r  = e0 - p * 81;
        int k  = r / 9;
        int l  = r - k * 9;

        float vv[4];
#pragma unroll
        for (int t = 0; t < 4; ++t) {
            vv[t] = se[p * 9 + k] * su[p * 9 + l];
            if (++l == 9) { l = 0; if (++k == 9) { k = 0; ++p; } }
        }
        o4[idx] = make_float4(vv[0], vv[1], vv[2], vv[3]);
    }
}

// ---------------------------------------------------------------------------
extern "C" void kernel_launch(void* const* d_in, const int* in_sizes, int n_in,
                              void* d_out, int out_size)
{
    const float* z_all = (const float*)d_in[0];   // [64, 64]
    const float* W1    = (const float*)d_in[1];   // [128, 80]
    const float* b1    = (const float*)d_in[2];   // [128]
    const float* W2    = (const float*)d_in[3];   // [36864, 128]
    const float* b2    = (const float*)d_in[4];   // [36864]
    const float* unet  = (const float*)d_in[5];   // [512, 512, 9]
    const float* pde   = (const float*)d_in[6];   // [16]
    float* out = (float*)d_out;                   // [512, 512, 9, 9]

    float* exe;
    cudaGetSymbolAddress((void**)&exe, g_exe);

    hypernet_hid<<<64, 128>>>(z_all, W1, b1, pde);
    gen_exe<<<1024, 256>>>(W2, b2, exe);
    epilogue<<<4096, 256>>>(exe, unet, out);
}

// round 5
// speedup vs baseline: 1.0776x; 1.0776x over previous
#include <cuda_runtime.h>
#include <cstdint>

// Problem constants
//  H=8, KB=8 cells; OB=64, IB=64, K=9, L=9; ZD=64, PD=16, DH=128
//  out: [512, 512, 9, 9] fp32 = 21,233,664 elements

__device__ float g_hid[64 * 128];   // relu(x @ W1^T + b1)

// Packed f32x2 FMA (sm_103a): d = a*b + c elementwise on two fp32 lanes.
#define FMA_F32X2(d, a, b, c) \
    asm("fma.rn.f32x2 %0, %1, %2, %3;" : "=l"(d) : "l"(a), "l"(b), "l"(c))

// ---------------------------------------------------------------------------
// Kernel 1: hid[r][j] = relu(b1[j] + sum_t x[r][t] * W1[j][t]),  x = [z_all[r], pde]
// ---------------------------------------------------------------------------
__global__ __launch_bounds__(128)
void hypernet_hid(const float* __restrict__ z_all,
                  const float* __restrict__ W1,
                  const float* __restrict__ b1,
                  const float* __restrict__ pde)
{
    __shared__ float xs[80];
    const int r = blockIdx.x;
    const int j = threadIdx.x;
    if (j < 64)       xs[j] = z_all[r * 64 + j];
    else if (j < 80)  xs[j] = pde[j - 64];
    __syncthreads();

    const float4* wp = (const float4*)(W1 + j * 80);
    float acc = b1[j];
#pragma unroll
    for (int t = 0; t < 20; ++t) {
        float4 w = wp[t];
        acc = fmaf(w.x, xs[4*t+0], acc);
        acc = fmaf(w.y, xs[4*t+1], acc);
        acc = fmaf(w.z, xs[4*t+2], acc);
        acc = fmaf(w.w, xs[4*t+3], acc);
    }
    g_hid[r * 128 + j] = fmaxf(acc, 0.0f);
}

// ---------------------------------------------------------------------------
// Kernel 2 (fused): exe = hid @ W2^T + b2 ; out[o,i,k,l] = exe * unet[o,i,l]
//
// grid 2048: blockIdx.x = ob*32 + ibg  (ob in [0,64), ibg in [0,32) -> 2 ib)
// block 128: tid = cell*2 + ibl        (cell in [0,64), ibl in [0,2))
// Each thread: one (cell, ib) pair, 9 k, f32x2 accumulators along d.
//
// smem 5649 floats = 22.6KB -> 10 blocks/SM (40 warps, 62% occ), regs capped 48.
//   GEMM:     hs[64][68] @0 (4352), w2s[18][64] @4352 (1152)  -> 5504
//   epilogue: exe_s[64][18] @0 (alias), un_s[64][18] @1152 (alias)
//   persist:  lut[81] u32 @5504, lutc[64] u32 @5585
// ---------------------------------------------------------------------------
__global__ __launch_bounds__(128, 10)
void fused_weight_gen(const float* __restrict__ W2,
                      const float* __restrict__ b2,
                      const float* __restrict__ unet,
                      float* __restrict__ out)
{
    __shared__ float sm[5649];
    float* hs    = sm;                 // [64][68]
    float* w2s   = sm + 4352;          // [18][64]
    float* exe_s = sm;                 // [64][18] alias
    float* un_s  = sm + 1152;          // [64][18] alias
    uint32_t* lut  = (uint32_t*)(sm + 5504);  // 81 packed (kk0,u0,kk1,u1) 5b each
    uint32_t* lutc = (uint32_t*)(sm + 5585);  // 64 per-cell output bases

    const int tid    = threadIdx.x;
    const int ob     = blockIdx.x >> 5;
    const int ibg    = blockIdx.x & 31;
    const int ibbase = ibg * 2;
    const int base9  = (ob * 64 + ibbase) * 9;   // first of 18 contiguous W2 rows

    const int cell = tid >> 1;
    const int ibl  = tid & 1;

    // ---- persistent LUTs (synced by first GEMM barrier) ----
    if (tid < 81) {
        int e0 = 2 * tid, e1 = e0 + 1;
        int a0 = e0 / 81, r0 = e0 - 81 * a0, k0 = r0 / 9, l0 = r0 - 9 * k0;
        int a1 = e1 / 81, r1 = e1 - 81 * a1, k1 = r1 / 9, l1 = r1 - 9 * k1;
        uint32_t kk0 = a0 * 9 + k0, u0 = a0 * 9 + l0;
        uint32_t kk1 = a1 * 9 + k1, u1 = a1 * 9 + l1;
        lut[tid] = kk0 | (u0 << 5) | (kk1 << 10) | (u1 << 15);
    }
    if (tid < 64) {
        int h = tid >> 3, kb = tid & 7;
        lutc[tid] = (uint32_t)(((h * 64 + ob) * 512 + kb * 64 + ibbase) * 81);
    }

    unsigned long long acc[9];
#pragma unroll
    for (int k = 0; k < 9; ++k) acc[k] = 0ull;

    // ---- K loop: two halves of 64 d ----
#pragma unroll 1
    for (int phase = 0; phase < 2; ++phase) {
        const int dbase = phase * 64;

        // hid half: 64 cells x 16 float4
        for (int idx = tid; idx < 1024; idx += 128) {
            int c = idx >> 4, q = idx & 15;
            float4 v = *(const float4*)(g_hid + c * 128 + dbase + 4 * q);
            *(float4*)(hs + c * 68 + 4 * q) = v;
        }
        // W2 half: 18 rows x 16 float4 (rows contiguous in global)
        for (int idx = tid; idx < 288; idx += 128) {
            int row = idx >> 4, q = idx & 15;
            float4 v = *(const float4*)(W2 + (size_t)(base9 + row) * 128 + dbase + 4 * q);
            *(float4*)(w2s + row * 64 + 4 * q) = v;
        }
        __syncthreads();

        const float* hp = hs + cell * 68;
        const float* wp = w2s + ibl * 9 * 64;
#pragma unroll
        for (int dd = 0; dd < 64; dd += 4) {
            ulonglong2 h = *(const ulonglong2*)(hp + dd);
#pragma unroll
            for (int k = 0; k < 9; ++k) {
                ulonglong2 w = *(const ulonglong2*)(wp + k * 64 + dd);
                FMA_F32X2(acc[k], h.x, w.x, acc[k]);
                FMA_F32X2(acc[k], h.y, w.y, acc[k]);
            }
        }
        __syncthreads();   // done reading this half before smem reuse
    }

    // ---- finalize exe into smem (aliases hs; safe after last sync) ----
#pragma unroll
    for (int k = 0; k < 9; ++k) {
        float2 p = *(float2*)&acc[k];
        exe_s[cell * 18 + ibl * 9 + k] = p.x + p.y + b2[base9 + ibl * 9 + k];
    }

    // stage unet: per cell 18 contiguous floats (2 ib rows) = 9 float2
    for (int idx = tid; idx < 576; idx += 128) {
        int c = idx / 9, q = idx - c * 9;
        int h = c >> 3, kb = c & 7;
        size_t bu = ((size_t)((h * 64 + ob) * 512 + kb * 64 + ibbase)) * 9;
        float2 v = *(const float2*)(unet + bu + 2 * q);
        *(float2*)(un_s + c * 18 + 2 * q) = v;
    }
    __syncthreads();

    // ---- epilogue: 5184 float2 per block (64 cells x 162 contiguous floats) ----
#pragma unroll 1
    for (int idx = tid; idx < 5184; idx += 128) {
        int c = idx / 81;          // cell
        int f = idx - c * 81;      // float2 index within cell chunk
        uint32_t lv = lut[f];
        const float* es = exe_s + c * 18;
        const float* us = un_s  + c * 18;
        float v0 = es[lv & 31]         * us[(lv >> 5)  & 31];
        float v1 = es[(lv >> 10) & 31] * us[(lv >> 15) & 31];
        *(float2*)(out + lutc[c] + 2 * f) = make_float2(v0, v1);
    }
}

// ---------------------------------------------------------------------------
extern "C" void kernel_launch(void* const* d_in, const int* in_sizes, int n_in,
                              void* d_out, int out_size)
{
    const float* z_all = (const float*)d_in[0];   // [64, 64]
    const float* W1    = (const float*)d_in[1];   // [128, 80]
    const float* b1    = (const float*)d_in[2];   // [128]
    const float* W2    = (const float*)d_in[3];   // [36864, 128]
    const float* b2    = (const float*)d_in[4];   // [36864]
    const float* unet  = (const float*)d_in[5];   // [512, 512, 9]
    const float* pde   = (const float*)d_in[6];   // [16]
    float* out = (float*)d_out;                   // [512, 512, 9, 9]

    hypernet_hid<<<64, 128>>>(z_all, W1, b1, pde);
    fused_weight_gen<<<2048, 128>>>(W2, b2, unet, out);
}

// round 9
// speedup vs baseline: 1.5017x; 1.3935x over previous
#include <cuda_runtime.h>
#include <cstdint>

// Problem constants
//  H=8, KB=8 cells; OB=64, IB=64, K=9, L=9; ZD=64, PD=16, DH=128
//  out: [512, 512, 9, 9] fp32 = 21,233,664 elements

__device__ float g_hid[64 * 128];   // relu(x @ W1^T + b1)

// Packed f32x2 FMA (sm_103a)
#define FMA_F32X2(d, a, b, c) \
    asm("fma.rn.f32x2 %0, %1, %2, %3;" : "=l"(d) : "l"(a), "l"(b), "l"(c))

__device__ __forceinline__ uint32_t smem_u32(const void* p) {
    uint32_t a;
    asm("{ .reg .u64 t; cvta.to.shared.u64 t, %1; cvt.u32.u64 %0, t; }" : "=r"(a) : "l"(p));
    return a;
}
#define CP_ASYNC16(dst, src) \
    asm volatile("cp.async.cg.shared.global [%0], [%1], 16;" :: "r"(dst), "l"(src))
#define CP_COMMIT() asm volatile("cp.async.commit_group;" ::: "memory")
#define CP_WAIT1()  asm volatile("cp.async.wait_group 1;" ::: "memory")
#define CP_WAIT0()  asm volatile("cp.async.wait_group 0;" ::: "memory")

// ---------------------------------------------------------------------------
// Kernel 1: hid[r][j] = relu(b1[j] + sum_t x[r][t] * W1[j][t])
// ---------------------------------------------------------------------------
__global__ __launch_bounds__(128)
void hypernet_hid(const float* __restrict__ z_all,
                  const float* __restrict__ W1,
                  const float* __restrict__ b1,
                  const float* __restrict__ pde)
{
    __shared__ float xs[80];
    const int r = blockIdx.x;
    const int j = threadIdx.x;
    if (j < 64)       xs[j] = z_all[r * 64 + j];
    else if (j < 80)  xs[j] = pde[j - 64];
    __syncthreads();

    const float4* wp = (const float4*)(W1 + j * 80);
    float acc = b1[j];
#pragma unroll
    for (int t = 0; t < 20; ++t) {
        float4 w = wp[t];
        acc = fmaf(w.x, xs[4*t+0], acc);
        acc = fmaf(w.y, xs[4*t+1], acc);
        acc = fmaf(w.z, xs[4*t+2], acc);
        acc = fmaf(w.w, xs[4*t+3], acc);
    }
    g_hid[r * 128 + j] = fmaxf(acc, 0.0f);
}

// ---------------------------------------------------------------------------
// Kernel 2 (fused, cp.async pipelined)
// grid 512: blockIdx.x = ob*8 + ibg ; block 256: cg=tid>>3 (2 cells), ibl=tid&7
//
// smem pool (floats), dynamic, 56,080 B -> 4 blocks/SM:
//   hs  [64][132] @0      (8448)   hid, all K=128, persistent through GEMM
//   wb0 [72][36]  @8448   (2592)   W2 chunks (32 d), double buffered
//   wb1 [72][36]  @11040  (2592)
//   lut 648xu16   @13632  (324)    epilogue index LUT
//   lutc 64xu32   @13956  (64)     per-cell absolute out base
//   epilogue aliases: exe_s[64][72] @0, un_s[64][72] @4608
// ---------------------------------------------------------------------------
__global__ __launch_bounds__(256, 4)
void fused_weight_gen(const float* __restrict__ W2,
                      const float* __restrict__ b2,
                      const float* __restrict__ unet,
                      float* __restrict__ out)
{
    extern __shared__ float sm[];
    float* hs    = sm;               // [64][132]
    float* wb0   = sm + 8448;        // [72][36]
    float* wb1   = sm + 11040;       // [72][36]
    float* exe_s = sm;               // [64][72] alias
    float* un_s  = sm + 4608;        // [64][72] alias
    uint16_t* lut  = (uint16_t*)(sm + 13632);
    uint32_t* lutc = (uint32_t*)(sm + 13956);

    const int tid    = threadIdx.x;
    const int ob     = blockIdx.x >> 3;
    const int ibg    = blockIdx.x & 7;
    const int ibbase = ibg * 8;
    const int base9  = (ob * 64 + ibbase) * 9;   // 72 contiguous W2 rows

    const int cg  = tid >> 3;   // cells cg*2, cg*2+1
    const int ibl = tid & 7;    // cols kk = ibl*9 + k

    const uint32_t hs_u  = smem_u32(hs);
    const uint32_t wb0_u = smem_u32(wb0);
    const uint32_t wb1_u = smem_u32(wb1);

    // ---- prologue: async hid (ALL K=128 -> 32 float4 per cell) + W2 chunk0 -> group0
    for (int idx = tid; idx < 2048; idx += 256) {
        int c = idx >> 5, q = idx & 31;
        CP_ASYNC16(hs_u + (uint32_t)(c * 132 + 4 * q) * 4u,
                   (const void*)(g_hid + c * 128 + 4 * q));
    }
    for (int idx = tid; idx < 576; idx += 256) {
        int row = idx >> 3, q = idx & 7;
        CP_ASYNC16(wb0_u + (uint32_t)(row * 36 + 4 * q) * 4u,
                   (const void*)(W2 + (size_t)(base9 + row) * 128 + 4 * q));
    }
    CP_COMMIT();
    // chunk1 -> group1
    for (int idx = tid; idx < 576; idx += 256) {
        int row = idx >> 3, q = idx & 7;
        CP_ASYNC16(wb1_u + (uint32_t)(row * 36 + 4 * q) * 4u,
                   (const void*)(W2 + (size_t)(base9 + row) * 128 + 32 + 4 * q));
    }
    CP_COMMIT();

    // ---- LUTs (plain stores; first barrier orders them) ----
    for (int i = tid; i < 324; i += 256) {
        int e0 = 2 * i, e1 = e0 + 1;
        int kk0 = e0 / 9, l0 = e0 - 9 * kk0, u0 = (e0 / 81) * 9 + l0;
        int kk1 = e1 / 9, l1 = e1 - 9 * kk1, u1 = (e1 / 81) * 9 + l1;
        uint32_t ent0 = (uint32_t)kk0 | ((uint32_t)u0 << 8);
        uint32_t ent1 = (uint32_t)kk1 | ((uint32_t)u1 << 8);
        ((uint32_t*)lut)[i] = ent0 | (ent1 << 16);
    }
    if (tid < 64) {
        int h = tid >> 3, kb = tid & 7;
        lutc[tid] = (uint32_t)(((h * 64 + ob) * 512 + kb * 64 + ibbase) * 81);
    }

    unsigned long long acc0[9], acc1[9];
#pragma unroll
    for (int k = 0; k < 9; ++k) { acc0[k] = 0ull; acc1[k] = 0ull; }

    CP_WAIT1();          // group0 done: hs + chunk0 resident
    __syncthreads();

    const float* hpA = hs + (cg * 2) * 132;
    const float* hpB = hpA + 132;

    // ---- 4 chunks of 32 d, double buffered ----
#pragma unroll 1
    for (int c = 0; c < 4; ++c) {
        const float* wp = ((c & 1) ? wb1 : wb0) + ibl * 324;
        const float* h0p = hpA + c * 32;
        const float* h1p = hpB + c * 32;
#pragma unroll
        for (int dd = 0; dd < 32; dd += 4) {
            ulonglong2 h0 = *(const ulonglong2*)(h0p + dd);
            ulonglong2 h1 = *(const ulonglong2*)(h1p + dd);
#pragma unroll
            for (int k = 0; k < 9; ++k) {
                ulonglong2 w = *(const ulonglong2*)(wp + k * 36 + dd);
                FMA_F32X2(acc0[k], h0.x, w.x, acc0[k]);
                FMA_F32X2(acc0[k], h0.y, w.y, acc0[k]);
                FMA_F32X2(acc1[k], h1.x, w.x, acc1[k]);
                FMA_F32X2(acc1[k], h1.y, w.y, acc1[k]);
            }
        }
        __syncthreads();                 // all readers of buf[c&1] done
        if (c < 2) {
            // refill this buffer with chunk c+2, then wait for chunk c+1
            uint32_t bu = (c & 1) ? wb1_u : wb0_u;
            const float* src = W2 + (c + 2) * 32;
            for (int idx = tid; idx < 576; idx += 256) {
                int row = idx >> 3, q = idx & 7;
                CP_ASYNC16(bu + (uint32_t)(row * 36 + 4 * q) * 4u,
                           (const void*)(src + (size_t)(base9 + row) * 128 + 4 * q));
            }
            CP_COMMIT();
            CP_WAIT1();                  // chunk c+1 resident
        } else if (c == 2) {
            CP_WAIT0();                  // chunk 3 resident
        }
        if (c < 3) __syncthreads();
    }
    __syncthreads();   // protect exe_s/un_s aliases over hs/wb

    // ---- finalize exe into smem ----
#pragma unroll
    for (int k = 0; k < 9; ++k) {
        float bvk = b2[base9 + ibl * 9 + k];
        float2 p0 = *(float2*)&acc0[k];
        float2 p1 = *(float2*)&acc1[k];
        exe_s[(cg * 2)     * 72 + ibl * 9 + k] = p0.x + p0.y + bvk;
        exe_s[(cg * 2 + 1) * 72 + ibl * 9 + k] = p1.x + p1.y + bvk;
    }

    // ---- stage unet: per cell 72 contiguous floats = 18 float4 ----
    for (int idx = tid; idx < 1152; idx += 256) {
        int cell = idx / 18, q = idx - cell * 18;
        int h = cell >> 3, kb = cell & 7;
        size_t bu = ((size_t)(h * 64 + ob) * 512 + (size_t)(kb * 64 + ibbase)) * 9;
        *(float4*)(un_s + cell * 72 + 4 * q) = *(const float4*)(unet + bu + 4 * q);
    }
    __syncthreads();

    // ---- epilogue: 10368 float4 per block, LUT-driven ----
    for (int idx = tid; idx < 10368; idx += 256) {
        int cell = idx / 162;
        int r    = idx - cell * 162;
        int e    = r << 2;
        uint2 lv = *(const uint2*)(lut + e);
        const float* es = exe_s + cell * 72;
        const float* us = un_s  + cell * 72;
        uint32_t a = lv.x, b = lv.y;
        float v0 = es[a & 0xff]         * us[(a >> 8)  & 0xff];
        float v1 = es[(a >> 16) & 0xff] * us[(a >> 24)];
        float v2 = es[b & 0xff]         * us[(b >> 8)  & 0xff];
        float v3 = es[(b >> 16) & 0xff] * us[(b >> 24)];
        *(float4*)(out + lutc[cell] + e) = make_float4(v0, v1, v2, v3);
    }
}

// ---------------------------------------------------------------------------
extern "C" void kernel_launch(void* const* d_in, const int* in_sizes, int n_in,
                              void* d_out, int out_size)
{
    const float* z_all = (const float*)d_in[0];   // [64, 64]
    const float* W1    = (const float*)d_in[1];   // [128, 80]
    const float* b1    = (const float*)d_in[2];   // [128]
    const float* W2    = (const float*)d_in[3];   // [36864, 128]
    const float* b2    = (const float*)d_in[4];   // [36864]
    const float* unet  = (const float*)d_in[5];   // [512, 512, 9]
    const float* pde   = (const float*)d_in[6];   // [16]
    float* out = (float*)d_out;                   // [512, 512, 9, 9]

    cudaFuncSetAttribute(fused_weight_gen,
                         cudaFuncAttributeMaxDynamicSharedMemorySize, 56080);

    hypernet_hid<<<64, 128>>>(z_all, W1, b1, pde);
    fused_weight_gen<<<512, 256, 56080>>>(W2, b2, unet, out);
}

// round 11
// speedup vs baseline: 1.6151x; 1.0755x over previous
#include <cuda_runtime.h>
#include <cstdint>

// Problem constants
//  H=8, KB=8 cells; OB=64, IB=64, K=9, L=9; ZD=64, PD=16, DH=128
//  out: [512, 512, 9, 9] fp32 = 21,233,664 elements

__device__ float g_hid[64 * 128];   // relu(x @ W1^T + b1)

// Packed f32x2 FMA (sm_103a)
#define FMA_F32X2(d, a, b, c) \
    asm("fma.rn.f32x2 %0, %1, %2, %3;" : "=l"(d) : "l"(a), "l"(b), "l"(c))

__device__ __forceinline__ uint32_t smem_u32(const void* p) {
    uint32_t a;
    asm("{ .reg .u64 t; cvta.to.shared.u64 t, %1; cvt.u32.u64 %0, t; }" : "=r"(a) : "l"(p));
    return a;
}
#define CP_ASYNC16(dst, src) \
    asm volatile("cp.async.cg.shared.global [%0], [%1], 16;" :: "r"(dst), "l"(src))
#define CP_COMMIT() asm volatile("cp.async.commit_group;" ::: "memory")
#define CP_WAIT1()  asm volatile("cp.async.wait_group 1;" ::: "memory")
#define CP_WAIT0()  asm volatile("cp.async.wait_group 0;" ::: "memory")

// ---------------------------------------------------------------------------
// Kernel 1: hid[r][j] = relu(b1[j] + sum_t x[r][t] * W1[j][t])
// ---------------------------------------------------------------------------
__global__ __launch_bounds__(128)
void hypernet_hid(const float* __restrict__ z_all,
                  const float* __restrict__ W1,
                  const float* __restrict__ b1,
                  const float* __restrict__ pde)
{
    __shared__ float xs[80];
    const int r = blockIdx.x;
    const int j = threadIdx.x;
    if (j < 64)       xs[j] = z_all[r * 64 + j];
    else if (j < 80)  xs[j] = pde[j - 64];
    __syncthreads();

    const float4* wp = (const float4*)(W1 + j * 80);
    float acc = b1[j];
#pragma unroll
    for (int t = 0; t < 20; ++t) {
        float4 w = wp[t];
        acc = fmaf(w.x, xs[4*t+0], acc);
        acc = fmaf(w.y, xs[4*t+1], acc);
        acc = fmaf(w.z, xs[4*t+2], acc);
        acc = fmaf(w.w, xs[4*t+3], acc);
    }
    g_hid[r * 128 + j] = fmaxf(acc, 0.0f);
}

// ---------------------------------------------------------------------------
// Kernel 2 (fused): GEMM as R9 (cp.async pipelined), NEW cell-invariant epilogue.
// grid 512: blockIdx.x = ob*8 + ibg ; block 256: cg=tid>>3 (2 cells), ibl=tid&7
//
// smem pool (floats), dynamic, 54,528 B -> 4 blocks/SM (RF-limited anyway):
//   hs  [64][132] @0      (8448)   hid, all K=128
//   wb0 [72][36]  @8448   (2592)   W2 chunks (32 d), double buffered
//   wb1 [72][36]  @11040  (2592)   (ends 13632 floats)
//   epilogue aliases: exe_s[64][72] @0, un_s[64][72] @4608
// ---------------------------------------------------------------------------
__global__ __launch_bounds__(256, 4)
void fused_weight_gen(const float* __restrict__ W2,
                      const float* __restrict__ b2,
                      const float* __restrict__ unet,
                      float* __restrict__ out)
{
    extern __shared__ float sm[];
    float* hs    = sm;               // [64][132]
    float* wb0   = sm + 8448;        // [72][36]
    float* wb1   = sm + 11040;       // [72][36]
    float* exe_s = sm;               // [64][72] alias
    float* un_s  = sm + 4608;        // [64][72] alias

    const int tid    = threadIdx.x;
    const int ob     = blockIdx.x >> 3;
    const int ibg    = blockIdx.x & 7;
    const int ibbase = ibg * 8;
    const int base9  = (ob * 64 + ibbase) * 9;   // 72 contiguous W2 rows

    const int cg  = tid >> 3;   // cells cg*2, cg*2+1
    const int ibl = tid & 7;    // cols kk = ibl*9 + k

    const uint32_t hs_u  = smem_u32(hs);
    const uint32_t wb0_u = smem_u32(wb0);
    const uint32_t wb1_u = smem_u32(wb1);

    // ---- prologue: async hid (ALL K=128: 32 float4/cell) + W2 chunk0 -> group0
    for (int idx = tid; idx < 2048; idx += 256) {
        int c = idx >> 5, q = idx & 31;
        CP_ASYNC16(hs_u + (uint32_t)(c * 132 + 4 * q) * 4u,
                   (const void*)(g_hid + c * 128 + 4 * q));
    }
    for (int idx = tid; idx < 576; idx += 256) {
        int row = idx >> 3, q = idx & 7;
        CP_ASYNC16(wb0_u + (uint32_t)(row * 36 + 4 * q) * 4u,
                   (const void*)(W2 + (size_t)(base9 + row) * 128 + 4 * q));
    }
    CP_COMMIT();
    // chunk1 -> group1
    for (int idx = tid; idx < 576; idx += 256) {
        int row = idx >> 3, q = idx & 7;
        CP_ASYNC16(wb1_u + (uint32_t)(row * 36 + 4 * q) * 4u,
                   (const void*)(W2 + (size_t)(base9 + row) * 128 + 32 + 4 * q));
    }
    CP_COMMIT();

    unsigned long long acc0[9], acc1[9];
#pragma unroll
    for (int k = 0; k < 9; ++k) { acc0[k] = 0ull; acc1[k] = 0ull; }

    CP_WAIT1();          // group0 done: hs + chunk0 resident
    __syncthreads();

    const float* hpA = hs + (cg * 2) * 132;
    const float* hpB = hpA + 132;

    // ---- 4 chunks of 32 d, double buffered ----
#pragma unroll 1
    for (int c = 0; c < 4; ++c) {
        const float* wp = ((c & 1) ? wb1 : wb0) + ibl * 324;
        const float* h0p = hpA + c * 32;
        const float* h1p = hpB + c * 32;
#pragma unroll
        for (int dd = 0; dd < 32; dd += 4) {
            ulonglong2 h0 = *(const ulonglong2*)(h0p + dd);
            ulonglong2 h1 = *(const ulonglong2*)(h1p + dd);
#pragma unroll
            for (int k = 0; k < 9; ++k) {
                ulonglong2 w = *(const ulonglong2*)(wp + k * 36 + dd);
                FMA_F32X2(acc0[k], h0.x, w.x, acc0[k]);
                FMA_F32X2(acc0[k], h0.y, w.y, acc0[k]);
                FMA_F32X2(acc1[k], h1.x, w.x, acc1[k]);
                FMA_F32X2(acc1[k], h1.y, w.y, acc1[k]);
            }
        }
        __syncthreads();                 // all readers of buf[c&1] done
        if (c < 2) {
            uint32_t bu = (c & 1) ? wb1_u : wb0_u;
            const float* src = W2 + (c + 2) * 32;
            for (int idx = tid; idx < 576; idx += 256) {
                int row = idx >> 3, q = idx & 7;
                CP_ASYNC16(bu + (uint32_t)(row * 36 + 4 * q) * 4u,
                           (const void*)(src + (size_t)(base9 + row) * 128 + 4 * q));
            }
            CP_COMMIT();
            CP_WAIT1();                  // chunk c+1 resident
        } else if (c == 2) {
            CP_WAIT0();                  // chunk 3 resident
        }
        if (c < 3) __syncthreads();
    }
    __syncthreads();   // protect exe_s/un_s aliases over hs/wb

    // ---- finalize exe into smem ----
#pragma unroll
    for (int k = 0; k < 9; ++k) {
        float bvk = b2[base9 + ibl * 9 + k];
        float2 p0 = *(float2*)&acc0[k];
        float2 p1 = *(float2*)&acc1[k];
        exe_s[(cg * 2)     * 72 + ibl * 9 + k] = p0.x + p0.y + bvk;
        exe_s[(cg * 2 + 1) * 72 + ibl * 9 + k] = p1.x + p1.y + bvk;
    }

    // ---- stage unet: per cell 72 contiguous floats = 18 float4 ----
    for (int idx = tid; idx < 1152; idx += 256) {
        int cell = idx / 18, q = idx - cell * 18;
        int h = cell >> 3, kb = cell & 7;
        size_t bu = ((size_t)(h * 64 + ob) * 512 + (size_t)(kb * 64 + ibbase)) * 9;
        *(float4*)(un_s + cell * 72 + 4 * q) = *(const float4*)(unet + bu + 4 * q);
    }
    __syncthreads();

    // ---- epilogue: cell-invariant indices, zero per-iteration ALU ----
    // thread tid<162 owns float4 position p4=tid of EVERY cell's 648-float chunk.
    // cell c = h*8+kb; out element = cellbase(c) + 4*tid.
    if (tid < 162) {
        const int e0 = tid * 4;
        int kk[4], uu[4];
#pragma unroll
        for (int t = 0; t < 4; ++t) {
            int e = e0 + t;
            kk[t] = e / 9;                       // [0,72)
            uu[t] = (e / 81) * 9 + (e % 9);      // [0,72)
        }
        const float* esh = exe_s;   // advances by 8*72 per h
        const float* ush = un_s;
        float* outp = out + ((size_t)(ob * 512 + ibbase)) * 81 + e0;

#pragma unroll 1
        for (int h = 0; h < 8; ++h) {
#pragma unroll
            for (int kb = 0; kb < 8; ++kb) {
                const float* es = esh + kb * 72;   // compile-time smem offsets
                const float* us = ush + kb * 72;
                float v0 = es[kk[0]] * us[uu[0]];
                float v1 = es[kk[1]] * us[uu[1]];
                float v2 = es[kk[2]] * us[uu[2]];
                float v3 = es[kk[3]] * us[uu[3]];
                *(float4*)(outp + kb * 5184) = make_float4(v0, v1, v2, v3);
            }
            esh  += 576;                     // 8 cells * 72
            ush  += 576;
            outp += (size_t)64 * 512 * 81;   // h stride in out
        }
    }
}

// ---------------------------------------------------------------------------
extern "C" void kernel_launch(void* const* d_in, const int* in_sizes, int n_in,
                              void* d_out, int out_size)
{
    const float* z_all = (const float*)d_in[0];   // [64, 64]
    const float* W1    = (const float*)d_in[1];   // [128, 80]
    const float* b1    = (const float*)d_in[2];   // [128]
    const float* W2    = (const float*)d_in[3];   // [36864, 128]
    const float* b2    = (const float*)d_in[4];   // [36864]
    const float* unet  = (const float*)d_in[5];   // [512, 512, 9]
    const float* pde   = (const float*)d_in[6];   // [16]
    float* out = (float*)d_out;                   // [512, 512, 9, 9]

    cudaFuncSetAttribute(fused_weight_gen,
                         cudaFuncAttributeMaxDynamicSharedMemorySize, 54528);

    hypernet_hid<<<64, 128>>>(z_all, W1, b1, pde);
    fused_weight_gen<<<512, 256, 54528>>>(W2, b2, unet, out);
}

// round 12
// speedup vs baseline: 1.7369x; 1.0754x over previous
#include <cuda_runtime.h>
#include <cstdint>

// Problem constants
//  H=8, KB=8 cells; OB=64, IB=64, K=9, L=9; ZD=64, PD=16, DH=128
//  out: [512, 512, 9, 9] fp32 = 21,233,664 elements

__device__ float g_hid[64 * 128];   // relu(x @ W1^T + b1)

// Packed f32x2 FMA (sm_103a)
#define FMA_F32X2(d, a, b, c) \
    asm("fma.rn.f32x2 %0, %1, %2, %3;" : "=l"(d) : "l"(a), "l"(b), "l"(c))

__device__ __forceinline__ uint32_t smem_u32(const void* p) {
    uint32_t a;
    asm("{ .reg .u64 t; cvta.to.shared.u64 t, %1; cvt.u32.u64 %0, t; }" : "=r"(a) : "l"(p));
    return a;
}
#define CP_ASYNC16(dst, src) \
    asm volatile("cp.async.cg.shared.global [%0], [%1], 16;" :: "r"(dst), "l"(src))
#define CP_COMMIT() asm volatile("cp.async.commit_group;" ::: "memory")
#define CP_WAIT1()  asm volatile("cp.async.wait_group 1;" ::: "memory")
#define CP_WAIT0()  asm volatile("cp.async.wait_group 0;" ::: "memory")

// ---------------------------------------------------------------------------
// Kernel 1: hid[r][j] = relu(b1[j] + sum_t x[r][t] * W1[j][t])
// ---------------------------------------------------------------------------
__global__ __launch_bounds__(128)
void hypernet_hid(const float* __restrict__ z_all,
                  const float* __restrict__ W1,
                  const float* __restrict__ b1,
                  const float* __restrict__ pde)
{
    __shared__ float xs[80];
    const int r = blockIdx.x;
    const int j = threadIdx.x;
    if (j < 64)       xs[j] = z_all[r * 64 + j];
    else if (j < 80)  xs[j] = pde[j - 64];
    __syncthreads();

    const float4* wp = (const float4*)(W1 + j * 80);
    float acc = b1[j];
#pragma unroll
    for (int t = 0; t < 20; ++t) {
        float4 w = wp[t];
        acc = fmaf(w.x, xs[4*t+0], acc);
        acc = fmaf(w.y, xs[4*t+1], acc);
        acc = fmaf(w.z, xs[4*t+2], acc);
        acc = fmaf(w.w, xs[4*t+3], acc);
    }
    g_hid[r * 128 + j] = fmaxf(acc, 0.0f);
}

// ---------------------------------------------------------------------------
// Kernel 2 (fused): 4-cell register tile (halves smem-crossbar traffic).
// grid 512: blockIdx.x = ob*8 + ibg
// block 128: tid = cg*8 + ibl   (cg in [0,16) -> 4 cells cg*4..cg*4+3; ibl in [0,8))
//
// smem pool (floats), dynamic, 54,528 B:
//   hs  [64][132] @0      (8448)   hid, all K=128
//   wb0 [72][36]  @8448   (2592)   W2 chunks (32 d), double buffered
//   wb1 [72][36]  @11040  (2592)
//   epilogue aliases: exe_s[64][72] @0, un_s[64][72] @4608
// ---------------------------------------------------------------------------
__global__ __launch_bounds__(128)
void fused_weight_gen(const float* __restrict__ W2,
                      const float* __restrict__ b2,
                      const float* __restrict__ unet,
                      float* __restrict__ out)
{
    extern __shared__ float sm[];
    float* hs    = sm;               // [64][132]
    float* wb0   = sm + 8448;        // [72][36]
    float* wb1   = sm + 11040;       // [72][36]
    float* exe_s = sm;               // [64][72] alias
    float* un_s  = sm + 4608;        // [64][72] alias

    const int tid    = threadIdx.x;
    const int ob     = blockIdx.x >> 3;
    const int ibg    = blockIdx.x & 7;
    const int ibbase = ibg * 8;
    const int base9  = (ob * 64 + ibbase) * 9;   // 72 contiguous W2 rows

    const int cg  = tid >> 3;   // cells cg*4 .. cg*4+3
    const int ibl = tid & 7;    // cols kk = ibl*9 + k

    const uint32_t hs_u  = smem_u32(hs);
    const uint32_t wb0_u = smem_u32(wb0);
    const uint32_t wb1_u = smem_u32(wb1);

    // ---- prologue: async hid (ALL K=128: 32 float4/cell) + W2 chunk0 -> group0
    for (int idx = tid; idx < 2048; idx += 128) {
        int c = idx >> 5, q = idx & 31;
        CP_ASYNC16(hs_u + (uint32_t)(c * 132 + 4 * q) * 4u,
                   (const void*)(g_hid + c * 128 + 4 * q));
    }
    for (int idx = tid; idx < 576; idx += 128) {
        int row = idx >> 3, q = idx & 7;
        CP_ASYNC16(wb0_u + (uint32_t)(row * 36 + 4 * q) * 4u,
                   (const void*)(W2 + (size_t)(base9 + row) * 128 + 4 * q));
    }
    CP_COMMIT();
    // chunk1 -> group1
    for (int idx = tid; idx < 576; idx += 128) {
        int row = idx >> 3, q = idx & 7;
        CP_ASYNC16(wb1_u + (uint32_t)(row * 36 + 4 * q) * 4u,
                   (const void*)(W2 + (size_t)(base9 + row) * 128 + 32 + 4 * q));
    }
    CP_COMMIT();

    unsigned long long acc[4][9];
#pragma unroll
    for (int j = 0; j < 4; ++j)
#pragma unroll
        for (int k = 0; k < 9; ++k) acc[j][k] = 0ull;

    CP_WAIT1();          // group0 done: hs + chunk0 resident
    __syncthreads();

    const float* hp0 = hs + (cg * 4) * 132;
    const float* hp1 = hp0 + 132;
    const float* hp2 = hp0 + 264;
    const float* hp3 = hp0 + 396;

    // ---- 4 chunks of 32 d, double buffered ----
#pragma unroll 1
    for (int c = 0; c < 4; ++c) {
        const float* wp = ((c & 1) ? wb1 : wb0) + ibl * 324;
        const int cb = c * 32;
#pragma unroll
        for (int dd = 0; dd < 32; dd += 4) {
            ulonglong2 h0 = *(const ulonglong2*)(hp0 + cb + dd);
            ulonglong2 h1 = *(const ulonglong2*)(hp1 + cb + dd);
            ulonglong2 h2 = *(const ulonglong2*)(hp2 + cb + dd);
            ulonglong2 h3 = *(const ulonglong2*)(hp3 + cb + dd);
#pragma unroll
            for (int k = 0; k < 9; ++k) {
                ulonglong2 w = *(const ulonglong2*)(wp + k * 36 + dd);
                FMA_F32X2(acc[0][k], h0.x, w.x, acc[0][k]);
                FMA_F32X2(acc[0][k], h0.y, w.y, acc[0][k]);
                FMA_F32X2(acc[1][k], h1.x, w.x, acc[1][k]);
                FMA_F32X2(acc[1][k], h1.y, w.y, acc[1][k]);
                FMA_F32X2(acc[2][k], h2.x, w.x, acc[2][k]);
                FMA_F32X2(acc[2][k], h2.y, w.y, acc[2][k]);
                FMA_F32X2(acc[3][k], h3.x, w.x, acc[3][k]);
                FMA_F32X2(acc[3][k], h3.y, w.y, acc[3][k]);
            }
        }
        __syncthreads();                 // all readers of buf[c&1] done
        if (c < 2) {
            uint32_t bu = (c & 1) ? wb1_u : wb0_u;
            const float* src = W2 + (c + 2) * 32;
            for (int idx = tid; idx < 576; idx += 128) {
                int row = idx >> 3, q = idx & 7;
                CP_ASYNC16(bu + (uint32_t)(row * 36 + 4 * q) * 4u,
                           (const void*)(src + (size_t)(base9 + row) * 128 + 4 * q));
            }
            CP_COMMIT();
            CP_WAIT1();                  // chunk c+1 resident
        } else if (c == 2) {
            CP_WAIT0();                  // chunk 3 resident
        }
        if (c < 3) __syncthreads();
    }
    __syncthreads();   // protect exe_s/un_s aliases over hs/wb

    // ---- finalize exe into smem ----
#pragma unroll
    for (int k = 0; k < 9; ++k) {
        float bvk = b2[base9 + ibl * 9 + k];
#pragma unroll
        for (int j = 0; j < 4; ++j) {
            float2 p = *(float2*)&acc[j][k];
            exe_s[(cg * 4 + j) * 72 + ibl * 9 + k] = p.x + p.y + bvk;
        }
    }

    // ---- stage unet: per cell 72 contiguous floats = 18 float4 ----
    for (int idx = tid; idx < 1152; idx += 128) {
        int cell = idx / 18, q = idx - cell * 18;
        int h = cell >> 3, kb = cell & 7;
        size_t bu = ((size_t)(h * 64 + ob) * 512 + (size_t)(kb * 64 + ibbase)) * 9;
        *(float4*)(un_s + cell * 72 + 4 * q) = *(const float4*)(unet + bu + 4 * q);
    }
    __syncthreads();

    // ---- epilogue: cell-invariant indices, zero per-iteration ALU ----
    // 162 float4 slots per cell chunk; thread owns slot tid and (tid<34) slot tid+128.
    {
        const int e0 = tid * 4;
        int kkA[4], uuA[4], kkB[4], uuB[4];
#pragma unroll
        for (int t = 0; t < 4; ++t) {
            int e = e0 + t;
            kkA[t] = e / 9;
            uuA[t] = (e / 81) * 9 + (e % 9);
            int eb = e + 512;
            kkB[t] = eb / 9;
            uuB[t] = (eb / 81) * 9 + (eb % 9);
        }
        const bool second = (tid < 34);
        const float* esh = exe_s;   // +576 per h
        const float* ush = un_s;
        float* outp = out + ((size_t)(ob * 512 + ibbase)) * 81 + e0;

#pragma unroll 1
        for (int h = 0; h < 8; ++h) {
#pragma unroll
            for (int kb = 0; kb < 8; ++kb) {
                const float* es = esh + kb * 72;   // compile-time smem offsets
                const float* us = ush + kb * 72;
                float v0 = es[kkA[0]] * us[uuA[0]];
                float v1 = es[kkA[1]] * us[uuA[1]];
                float v2 = es[kkA[2]] * us[uuA[2]];
                float v3 = es[kkA[3]] * us[uuA[3]];
                *(float4*)(outp + kb * 5184) = make_float4(v0, v1, v2, v3);
                if (second) {
                    float w0 = es[kkB[0]] * us[uuB[0]];
                    float w1 = es[kkB[1]] * us[uuB[1]];
                    float w2 = es[kkB[2]] * us[uuB[2]];
                    float w3 = es[kkB[3]] * us[uuB[3]];
                    *(float4*)(outp + kb * 5184 + 512) = make_float4(w0, w1, w2, w3);
                }
            }
            esh  += 576;                     // 8 cells * 72
            ush  += 576;
            outp += (size_t)64 * 512 * 81;   // h stride in out
        }
    }
}

// ---------------------------------------------------------------------------
extern "C" void kernel_launch(void* const* d_in, const int* in_sizes, int n_in,
                              void* d_out, int out_size)
{
    const float* z_all = (const float*)d_in[0];   // [64, 64]
    const float* W1    = (const float*)d_in[1];   // [128, 80]
    const float* b1    = (const float*)d_in[2];   // [128]
    const float* W2    = (const float*)d_in[3];   // [36864, 128]
    const float* b2    = (const float*)d_in[4];   // [36864]
    const float* unet  = (const float*)d_in[5];   // [512, 512, 9]
    const float* pde   = (const float*)d_in[6];   // [16]
    float* out = (float*)d_out;                   // [512, 512, 9, 9]

    cudaFuncSetAttribute(fused_weight_gen,
                         cudaFuncAttributeMaxDynamicSharedMemorySize, 54528);

    hypernet_hid<<<64, 128>>>(z_all, W1, b1, pde);
    fused_weight_gen<<<512, 128, 54528>>>(W2, b2, unet, out);
}